// round 10
// baseline (speedup 1.0000x reference)
#include <cuda_runtime.h>
#include <cuda_bf16.h>
#include <cstdint>

#define BB 16
#define CC 512
#define PP 1024
#define OC 1536   // concatenated q|k|v output channels

// fp8 e4m3 storage
typedef uint8_t fp8;

// ---------------------------------------------------------------------------
// Static device scratch
// ---------------------------------------------------------------------------
__device__ __align__(1024) fp8 g_nT[(size_t)BB * PP * CC];     // [b][p][c]
__device__ __align__(1024) fp8 g_qkvT[(size_t)BB * PP * OC];   // [b][p][o]
__device__ __align__(1024) fp8 g_WT[4 * CC * CC];              // [which][o][c], x16 scaled
__device__ __align__(128)  float g_part[(size_t)BB * 64 * 1024];
__device__ __align__(128)  float g_num[BB * 1024];
__device__ __align__(128)  float g_diag[BB * PP];
__device__ __align__(128)  float g_bcat[OC];

#define WSCALE     16.0f
#define INV_WSCALE 0.0625f

// ---------------------------------------------------------------------------
// helpers
// ---------------------------------------------------------------------------
__device__ __forceinline__ uint32_t smem_u32(const void* p) {
    uint32_t a;
    asm("{ .reg .u64 t; cvta.to.shared.u64 t, %1; cvt.u32.u64 %0, t; }"
        : "=r"(a) : "l"(p));
    return a;
}

// pack two floats -> e4m3x2 (low byte = lo, high byte = hi)
__device__ __forceinline__ uint16_t pack_e4m3(float lo, float hi) {
    uint16_t r;
    asm("cvt.rn.satfinite.e4m3x2.f32 %0, %1, %2;" : "=h"(r) : "f"(hi), "f"(lo));
    return r;
}

#define CPA16(sm, gm) \
    asm volatile("cp.async.cg.shared.global [%0], [%1], 16;" \
                 :: "r"(sm), "l"(gm))

__device__ __forceinline__ void ldsm4(uint32_t* r, uint32_t a) {
    asm volatile("ldmatrix.sync.aligned.m8n8.x4.shared.b16 {%0,%1,%2,%3}, [%4];"
                 : "=r"(r[0]), "=r"(r[1]), "=r"(r[2]), "=r"(r[3]) : "r"(a));
}

__device__ __forceinline__ void mma16832(float* c, const uint32_t* a,
                                         uint32_t b0, uint32_t b1) {
    asm volatile(
        "mma.sync.aligned.m16n8k32.row.col.f32.e4m3.e4m3.f32 "
        "{%0,%1,%2,%3}, {%4,%5,%6,%7}, {%8,%9}, {%0,%1,%2,%3};"
        : "+f"(c[0]), "+f"(c[1]), "+f"(c[2]), "+f"(c[3])
        : "r"(a[0]), "r"(a[1]), "r"(a[2]), "r"(a[3]), "r"(b0), "r"(b1));
}

// smem tile: 128 rows x 80 bytes (64B data = 64 fp8, + 16B pad)
#define ROWB   80
#define TILEB  (128 * ROWB)
#define SMEM_BYTES (3 * 2 * TILEB)   // 61440

// ---------------------------------------------------------------------------
// Weight transpose: WT[o][c] = fp8(W[c][o] * 16)
// ---------------------------------------------------------------------------
__global__ void wt_kernel(const float* __restrict__ Wq, const float* __restrict__ Wk,
                          const float* __restrict__ Wv, const float* __restrict__ Wn,
                          fp8* __restrict__ WT)
{
    const float* srcs[4] = {Wq, Wk, Wv, Wn};
    const float* W = srcs[blockIdx.z];
    fp8* dst = WT + (size_t)blockIdx.z * CC * CC;
    __shared__ float t[32][33];
    int c0 = blockIdx.x * 32, o0 = blockIdx.y * 32;
    for (int i = threadIdx.y; i < 32; i += 8)
        t[i][threadIdx.x] = W[(size_t)(c0 + i) * CC + o0 + threadIdx.x];
    __syncthreads();
    for (int i = threadIdx.y; i < 32; i += 8) {
        uint16_t p = pack_e4m3(t[threadIdx.x][i] * WSCALE, 0.f);
        dst[(size_t)(o0 + i) * CC + c0 + threadIdx.x] = (fp8)(p & 0xFF);
    }
}

__global__ void bcat_kernel(const float* __restrict__ bq, const float* __restrict__ bk,
                            const float* __restrict__ bv, float* __restrict__ bc)
{
    int i = blockIdx.x * 256 + threadIdx.x;
    if (i < CC) {
        bc[i] = bq[i];
        bc[CC + i] = bk[i];
        bc[2 * CC + i] = bv[i];
    }
}

// ---------------------------------------------------------------------------
// GroupNorm -> transposed fp8 output nT[b][p][c]
// ---------------------------------------------------------------------------
__global__ void gn_kernel(const float* __restrict__ x, fp8* __restrict__ nT)
{
    int b = blockIdx.x >> 5;
    int g = blockIdx.x & 31;
    const float* xp = x + ((size_t)b * CC + g * 16) * PP;

    float s = 0.f, s2 = 0.f;
    for (int i = threadIdx.x; i < 16384; i += 256) {
        float v = xp[i];
        s += v; s2 += v * v;
    }
    __shared__ float sh1[256], sh2[256];
    sh1[threadIdx.x] = s; sh2[threadIdx.x] = s2;
    __syncthreads();
    for (int off = 128; off; off >>= 1) {
        if (threadIdx.x < off) {
            sh1[threadIdx.x] += sh1[threadIdx.x + off];
            sh2[threadIdx.x] += sh2[threadIdx.x + off];
        }
        __syncthreads();
    }
    float mean = sh1[0] * (1.f / 16384.f);
    float var  = sh2[0] * (1.f / 16384.f) - mean * mean;
    float inv  = rsqrtf(var + 1e-5f);

    fp8* np = nT + (size_t)b * PP * CC + g * 16;
    for (int p = threadIdx.x; p < PP; p += 256) {
        uint16_t h[8];
#pragma unroll
        for (int cc = 0; cc < 16; cc += 2) {
            float v0 = (xp[(size_t)cc * PP + p] - mean) * inv;
            float v1 = (xp[(size_t)(cc + 1) * PP + p] - mean) * inv;
            h[cc >> 1] = pack_e4m3(v0, v1);
        }
        uint4 pk;
        pk.x = (uint32_t)h[0] | ((uint32_t)h[1] << 16);
        pk.y = (uint32_t)h[2] | ((uint32_t)h[3] << 16);
        pk.z = (uint32_t)h[4] | ((uint32_t)h[5] << 16);
        pk.w = (uint32_t)h[6] | ((uint32_t)h[7] << 16);
        *(uint4*)(np + (size_t)p * CC) = pk;
    }
}

// ---------------------------------------------------------------------------
// FP8 MMA GEMM: D[m][n] = sum_{k<512} A[m][k]*B[n][k]; K-contig fp8 operands.
// CTA 128x128, warp 32x64 (4x2), K slab 64 fp8 (8 slabs), 3-stage cp.async.
// MODE 0: fp8 C[p][o] = (D*1/16) + bias[o], ldc=1536  (merged q|k|v; W x16)
// MODE 1: fused exp -> g_part / g_num                 (scores, no W scale)
// MODE 2: fp32 out[o][p] = x + bias[o] + diag[p]*(D/16), smem-transposed
// ---------------------------------------------------------------------------
template <int MODE>
__global__ __launch_bounds__(256)
void gemm_mma(const fp8* __restrict__ A, long long sA, int ldaA,
              const fp8* __restrict__ Bm, long long sB, int ldaB,
              void* __restrict__ Cout,
              const float* __restrict__ bias, const float* __restrict__ xres,
              const float* __restrict__ dgv,
              float* __restrict__ part, float* __restrict__ num)
{
    extern __shared__ char smem[];
    uint32_t s0 = smem_u32(smem);

    int tid = threadIdx.x, lane = tid & 31, wid = tid >> 5;
    int wm = wid & 3, wn = wid >> 2;
    int b = blockIdx.z;
    int m0 = blockIdx.x * 128, n0 = blockIdx.y * 128;

    const char* Ab = (const char*)A + (size_t)b * sA + (size_t)m0 * ldaA;
    const char* Bb = (const char*)Bm + (size_t)b * sB + (size_t)n0 * ldaB;

    // cp.async: 512 x 16B chunks per tile, 2 per thread; 4 chunks (64B) per row
    int ra0 = tid >> 2, ca0 = tid & 3;
    int ra1 = (tid + 256) >> 2, ca1 = (tid + 256) & 3;
    uint32_t sm0 = (uint32_t)(ra0 * ROWB + ca0 * 16);
    uint32_t sm1 = (uint32_t)(ra1 * ROWB + ca1 * 16);
    int gA0 = ra0 * ldaA + ca0 * 16;
    int gA1 = ra1 * ldaA + ca1 * 16;
    int gB0 = ra0 * ldaB + ca0 * 16;
    int gB1 = ra1 * ldaB + ca1 * 16;

    uint32_t aoff[2][2], boff[2][4];
    {
        int ar = wm * 32 + (lane & 15);
        int ac = (lane >> 4);
#pragma unroll
        for (int mr = 0; mr < 2; mr++)
#pragma unroll
            for (int ks = 0; ks < 2; ks++)
                aoff[mr][ks] = (uint32_t)((ar + mr * 16) * ROWB + (ks * 2 + ac) * 16);
        int br = wn * 64 + ((lane >> 4) & 1) * 8 + (lane & 7);
        int bc = (lane >> 3) & 1;
#pragma unroll
        for (int ks = 0; ks < 2; ks++)
#pragma unroll
            for (int p = 0; p < 4; p++)
                boff[ks][p] = (uint32_t)((br + p * 16) * ROWB + (ks * 2 + bc) * 16);
    }

    float acc[2][8][4];
#pragma unroll
    for (int i = 0; i < 2; i++)
#pragma unroll
        for (int j = 0; j < 8; j++)
#pragma unroll
            for (int l = 0; l < 4; l++) acc[i][j][l] = 0.f;

    auto issue = [&](int s, int st) {
        uint32_t ab = s0 + (uint32_t)st * (2 * TILEB);
        uint32_t bb = ab + TILEB;
        const char* ga = Ab + s * 64;
        const char* gb = Bb + s * 64;
        CPA16(ab + sm0, ga + gA0);
        CPA16(ab + sm1, ga + gA1);
        CPA16(bb + sm0, gb + gB0);
        CPA16(bb + sm1, gb + gB1);
        asm volatile("cp.async.commit_group;" ::: "memory");
    };

    issue(0, 0);
    issue(1, 1);

    for (int s = 0; s < 8; s++) {
        if (s < 7) asm volatile("cp.async.wait_group 1;" ::: "memory");
        else       asm volatile("cp.async.wait_group 0;" ::: "memory");
        __syncthreads();
        if (s + 2 < 8) issue(s + 2, (s + 2) % 3);

        uint32_t ab = s0 + (uint32_t)(s % 3) * (2 * TILEB);
        uint32_t bb = ab + TILEB;

#pragma unroll
        for (int ks = 0; ks < 2; ks++) {
            uint32_t af[2][4], bfr[4][4];
            ldsm4(af[0], ab + aoff[0][ks]);
            ldsm4(af[1], ab + aoff[1][ks]);
#pragma unroll
            for (int p = 0; p < 4; p++)
                ldsm4(bfr[p], bb + boff[ks][p]);
#pragma unroll
            for (int mr = 0; mr < 2; mr++)
#pragma unroll
                for (int nt = 0; nt < 8; nt++)
                    mma16832(acc[mr][nt], af[mr],
                             bfr[nt >> 1][(nt & 1) * 2], bfr[nt >> 1][(nt & 1) * 2 + 1]);
        }
    }

    // ---------------- epilogues ----------------
    int row0 = m0 + wm * 32;
    int col0 = n0 + wn * 64;
    int tr = lane >> 2, tc = (lane & 3) * 2;

    if (MODE == 0) {
        fp8* Cb = (fp8*)Cout + (size_t)b * ((size_t)PP * OC);
#pragma unroll
        for (int mr = 0; mr < 2; mr++) {
            int p1 = row0 + mr * 16 + tr, p2 = p1 + 8;
#pragma unroll
            for (int nt = 0; nt < 8; nt++) {
                int o = col0 + nt * 8 + tc;
                float b0 = bias[o], b1 = bias[o + 1];
                uint16_t v01 = pack_e4m3(acc[mr][nt][0] * INV_WSCALE + b0,
                                         acc[mr][nt][1] * INV_WSCALE + b1);
                uint16_t v23 = pack_e4m3(acc[mr][nt][2] * INV_WSCALE + b0,
                                         acc[mr][nt][3] * INV_WSCALE + b1);
                *(uint16_t*)(Cb + (size_t)p1 * OC + o) = v01;
                *(uint16_t*)(Cb + (size_t)p2 * OC + o) = v23;
            }
        }
    } else if (MODE == 1) {
        const float scale = 0.04419417382415922f;   // 512^-0.5
        __syncthreads();   // protect smem stages still being read
#pragma unroll
        for (int mr = 0; mr < 2; mr++)
#pragma unroll
            for (int nt = 0; nt < 8; nt++)
#pragma unroll
                for (int l = 0; l < 4; l++) {
                    float e = __expf(scale * acc[mr][nt][l]);
                    acc[mr][nt][l] = e;
                    int p = row0 + mr * 16 + tr + ((l >> 1) * 8);
                    int n = col0 + nt * 8 + tc + (l & 1);
                    if (((p >> 5) == (p & 31)) && ((n >> 5) == (n & 31)))
                        num[b * 1024 + (p & 31) * 32 + (n & 31)] = e;
                }
        float* sp = (float*)smem;   // 8 warps x 1024 bins
#pragma unroll
        for (int mr = 0; mr < 2; mr++)
#pragma unroll
            for (int rt = 0; rt < 2; rt++) {
                int i = mr * 16 + tr + rt * 8;
#pragma unroll
                for (int nt4 = 0; nt4 < 4; nt4++)
#pragma unroll
                    for (int ct = 0; ct < 2; ct++) {
                        int j = nt4 * 8 + tc + ct;
                        sp[wid * 1024 + i * 32 + j] =
                            acc[mr][nt4][rt * 2 + ct] + acc[mr][nt4 + 4][rt * 2 + ct];
                    }
            }
        __syncthreads();
        float* pb = part + ((size_t)(b * 64 + blockIdx.y * 8 + blockIdx.x)) * 1024;
        for (int ij = tid; ij < 1024; ij += 256) {
            float sum = 0.f;
#pragma unroll
            for (int w = 0; w < 8; w++) sum += sp[w * 1024 + ij];
            pb[ij] = sum;
        }
    } else {
        float* ob = (float*)Cout + (size_t)b * ((size_t)CC * PP);
        const float* xb = xres + (size_t)b * ((size_t)CC * PP);
        float dg1[2], dg2[2];
#pragma unroll
        for (int mr = 0; mr < 2; mr++) {
            dg1[mr] = dgv[b * PP + row0 + mr * 16 + tr] * INV_WSCALE;
            dg2[mr] = dgv[b * PP + row0 + mr * 16 + tr + 8] * INV_WSCALE;
        }
        float (*tp)[132] = (float(*)[132])smem;
        for (int h = 0; h < 2; h++) {
            __syncthreads();
            if (wn == h) {
#pragma unroll
                for (int mr = 0; mr < 2; mr++)
#pragma unroll
                    for (int nt = 0; nt < 8; nt++)
#pragma unroll
                        for (int l = 0; l < 4; l++) {
                            int o_in = nt * 8 + tc + (l & 1);
                            int p_l = wm * 32 + mr * 16 + tr + ((l >> 1) * 8);
                            float dg = (l >> 1) ? dg2[mr] : dg1[mr];
                            tp[o_in][p_l] = dg * acc[mr][nt][l];
                        }
            }
            __syncthreads();
            int r = tid >> 2;
            int cb = (tid & 3) * 32;
            int o = n0 + h * 64 + r;
            float bv = bias[o];
            size_t base = (size_t)o * PP + m0;
#pragma unroll
            for (int k = 0; k < 8; k++) {
                int c = cb + k * 4;
                float4 xv = *(const float4*)(xb + base + c);
                float4 w;
                w.x = xv.x + bv + tp[r][c];
                w.y = xv.y + bv + tp[r][c + 1];
                w.z = xv.z + bv + tp[r][c + 2];
                w.w = xv.w + bv + tp[r][c + 3];
                *(float4*)(ob + base + c) = w;
            }
        }
    }
}

// ---------------------------------------------------------------------------
// diag = num / sum(part)  (fixed order over 64 tiles -> deterministic)
// ---------------------------------------------------------------------------
__global__ void diag_kernel(const float* __restrict__ part,
                            const float* __restrict__ num,
                            float* __restrict__ diag)
{
    int idx = blockIdx.x * 256 + threadIdx.x;   // 16384 total
    int b = idx >> 10, ij = idx & 1023;
    const float* pp = part + (size_t)b * 64 * 1024 + ij;
    float s = 0.f;
#pragma unroll
    for (int t = 0; t < 64; t++) s += pp[t * 1024];
    diag[idx] = num[idx] / s;
}

// ---------------------------------------------------------------------------
// kernel_launch — inputs: x, Wq, bq, Wk, bk, Wv, bv, Wn, bn
// ---------------------------------------------------------------------------
extern "C" void kernel_launch(void* const* d_in, const int* in_sizes, int n_in,
                              void* d_out, int out_size)
{
    const float* x  = (const float*)d_in[0];
    const float* Wq = (const float*)d_in[1];
    const float* bq = (const float*)d_in[2];
    const float* Wk = (const float*)d_in[3];
    const float* bk = (const float*)d_in[4];
    const float* Wv = (const float*)d_in[5];
    const float* bv = (const float*)d_in[6];
    const float* Wn = (const float*)d_in[7];
    const float* bn = (const float*)d_in[8];
    float* out = (float*)d_out;

    fp8 *pnT, *pqkv, *pWT;
    float *ppart, *pnum, *pdiag, *pbcat;
    cudaGetSymbolAddress((void**)&pnT, g_nT);
    cudaGetSymbolAddress((void**)&pqkv, g_qkvT);
    cudaGetSymbolAddress((void**)&pWT, g_WT);
    cudaGetSymbolAddress((void**)&ppart, g_part);
    cudaGetSymbolAddress((void**)&pnum, g_num);
    cudaGetSymbolAddress((void**)&pdiag, g_diag);
    cudaGetSymbolAddress((void**)&pbcat, g_bcat);

    cudaFuncSetAttribute(gemm_mma<0>, cudaFuncAttributeMaxDynamicSharedMemorySize, SMEM_BYTES);
    cudaFuncSetAttribute(gemm_mma<1>, cudaFuncAttributeMaxDynamicSharedMemorySize, SMEM_BYTES);
    cudaFuncSetAttribute(gemm_mma<2>, cudaFuncAttributeMaxDynamicSharedMemorySize, SMEM_BYTES);

    // 1. Weight transposes (x16 into fp8) + bias concat
    wt_kernel<<<dim3(16, 16, 4), dim3(32, 8)>>>(Wq, Wk, Wv, Wn, pWT);
    bcat_kernel<<<2, 256>>>(bq, bk, bv, pbcat);

    // 2. GroupNorm -> nT fp8
    gn_kernel<<<BB * 32, 256>>>(x, pnT);

    // 3. Merged q|k|v projection (fp8 out)
    dim3 gp(8, 12, BB);
    gemm_mma<0><<<gp, 256, SMEM_BYTES>>>(pnT, (long long)PP * CC, CC,
                                         pWT, 0, CC,
                                         pqkv, pbcat, nullptr, nullptr,
                                         nullptr, nullptr);

    // 4. Scores with fused exp epilogue
    dim3 gs(8, 8, BB);
    gemm_mma<1><<<gs, 256, SMEM_BYTES>>>(pqkv, (long long)PP * OC, OC,
                                         pqkv + CC, (long long)PP * OC, OC,
                                         nullptr, nullptr, nullptr, nullptr,
                                         ppart, pnum);

    // 5. diag = num / denom
    diag_kernel<<<64, 256>>>(ppart, pnum, pdiag);

    // 6. Final fused projection — grid FIXED: 4 n-tiles cover all 512 channels
    dim3 gf(8, 4, BB);
    gemm_mma<2><<<gf, 256, SMEM_BYTES>>>(pqkv + 2 * CC, (long long)PP * OC, OC,
                                         pWT + 3 * CC * CC, 0, CC,
                                         out, bn, x, pdiag,
                                         nullptr, nullptr);
}

// round 12
// speedup vs baseline: 1.2251x; 1.2251x over previous
#include <cuda_runtime.h>
#include <cuda_bf16.h>
#include <cstdint>

#define BB 16
#define CC 512
#define PP 1024
#define OC 1536   // concatenated q|k|v output channels

typedef __nv_bfloat16 bf16;

// ---------------------------------------------------------------------------
// Static device scratch
// ---------------------------------------------------------------------------
__device__ __align__(1024) bf16 g_nT[(size_t)BB * PP * CC];     // [b][p][c]
__device__ __align__(1024) bf16 g_qkvT[(size_t)BB * PP * OC];   // [b][p][o]
__device__ __align__(1024) bf16 g_WT[4 * CC * CC];              // [which][o][c]
__device__ __align__(128)  float g_part[(size_t)BB * 64 * 1024];
__device__ __align__(128)  float g_num[BB * 1024];
__device__ __align__(128)  float g_diag[BB * PP];
__device__ __align__(128)  float g_bcat[OC];

// ---------------------------------------------------------------------------
// helpers
// ---------------------------------------------------------------------------
__device__ __forceinline__ uint32_t smem_u32(const void* p) {
    uint32_t a;
    asm("{ .reg .u64 t; cvta.to.shared.u64 t, %1; cvt.u32.u64 %0, t; }"
        : "=r"(a) : "l"(p));
    return a;
}

#define CPA16(sm, gm) \
    asm volatile("cp.async.cg.shared.global [%0], [%1], 16;" \
                 :: "r"(sm), "l"(gm))

__device__ __forceinline__ void ldsm4(uint32_t* r, uint32_t a) {
    asm volatile("ldmatrix.sync.aligned.m8n8.x4.shared.b16 {%0,%1,%2,%3}, [%4];"
                 : "=r"(r[0]), "=r"(r[1]), "=r"(r[2]), "=r"(r[3]) : "r"(a));
}

__device__ __forceinline__ void mma16816(float* c, const uint32_t* a,
                                         uint32_t b0, uint32_t b1) {
    asm volatile(
        "mma.sync.aligned.m16n8k16.row.col.f32.bf16.bf16.f32 "
        "{%0,%1,%2,%3}, {%4,%5,%6,%7}, {%8,%9}, {%0,%1,%2,%3};"
        : "+f"(c[0]), "+f"(c[1]), "+f"(c[2]), "+f"(c[3])
        : "r"(a[0]), "r"(a[1]), "r"(a[2]), "r"(a[3]), "r"(b0), "r"(b1));
}

// smem tile: 128 rows x 80 bytes (64B data + 16B pad) -> conflict-free ldmatrix
#define ROWB   80
#define TILEB  (128 * ROWB)          // 10240
#define SMEM_BYTES (3 * 2 * TILEB)   // 61440

// ---------------------------------------------------------------------------
// Weight transpose: WT[o][c] = bf16(W[c][o]); q|k|v|n concat
// ---------------------------------------------------------------------------
__global__ void wt_kernel(const float* __restrict__ Wq, const float* __restrict__ Wk,
                          const float* __restrict__ Wv, const float* __restrict__ Wn,
                          bf16* __restrict__ WT)
{
    const float* srcs[4] = {Wq, Wk, Wv, Wn};
    const float* W = srcs[blockIdx.z];
    bf16* dst = WT + (size_t)blockIdx.z * CC * CC;
    __shared__ float t[32][33];
    int c0 = blockIdx.x * 32, o0 = blockIdx.y * 32;
    for (int i = threadIdx.y; i < 32; i += 8)
        t[i][threadIdx.x] = W[(size_t)(c0 + i) * CC + o0 + threadIdx.x];
    __syncthreads();
    for (int i = threadIdx.y; i < 32; i += 8)
        dst[(size_t)(o0 + i) * CC + c0 + threadIdx.x] =
            __float2bfloat16(t[threadIdx.x][i]);
}

__global__ void bcat_kernel(const float* __restrict__ bq, const float* __restrict__ bk,
                            const float* __restrict__ bv, float* __restrict__ bc)
{
    int i = blockIdx.x * 256 + threadIdx.x;
    if (i < CC) {
        bc[i] = bq[i];
        bc[CC + i] = bk[i];
        bc[2 * CC + i] = bv[i];
    }
}

// ---------------------------------------------------------------------------
// GroupNorm -> transposed bf16 output nT[b][p][c]
// ---------------------------------------------------------------------------
__global__ void gn_kernel(const float* __restrict__ x, bf16* __restrict__ nT)
{
    int b = blockIdx.x >> 5;
    int g = blockIdx.x & 31;
    const float* xp = x + ((size_t)b * CC + g * 16) * PP;

    float s = 0.f, s2 = 0.f;
    for (int i = threadIdx.x; i < 16384; i += 256) {
        float v = xp[i];
        s += v; s2 += v * v;
    }
    __shared__ float sh1[256], sh2[256];
    sh1[threadIdx.x] = s; sh2[threadIdx.x] = s2;
    __syncthreads();
    for (int off = 128; off; off >>= 1) {
        if (threadIdx.x < off) {
            sh1[threadIdx.x] += sh1[threadIdx.x + off];
            sh2[threadIdx.x] += sh2[threadIdx.x + off];
        }
        __syncthreads();
    }
    float mean = sh1[0] * (1.f / 16384.f);
    float var  = sh2[0] * (1.f / 16384.f) - mean * mean;
    float inv  = rsqrtf(var + 1e-5f);

    bf16* np = nT + (size_t)b * PP * CC + g * 16;
    for (int p = threadIdx.x; p < PP; p += 256) {
        uint32_t pk[8];
#pragma unroll
        for (int cc = 0; cc < 16; cc += 2) {
            float v0 = (xp[(size_t)cc * PP + p] - mean) * inv;
            float v1 = (xp[(size_t)(cc + 1) * PP + p] - mean) * inv;
            __nv_bfloat162 h = __floats2bfloat162_rn(v0, v1);
            pk[cc >> 1] = *(uint32_t*)&h;
        }
        uint4* dst = (uint4*)(np + (size_t)p * CC);
        dst[0] = make_uint4(pk[0], pk[1], pk[2], pk[3]);
        dst[1] = make_uint4(pk[4], pk[5], pk[6], pk[7]);
    }
}

// ---------------------------------------------------------------------------
// HMMA GEMM: D[m][n] = sum_{k<512} A[m][k]*B[n][k], K-contig bf16 operands.
// CTA 128x128, warp tile 64x64 (2x2 warps, 128 threads), K slab 32, 3-stage.
// MODE 0: bf16 C[p][o] = D + bias[o], ldc=1536   (merged q|k|v proj)
// MODE 1: fused exp -> g_part / g_num            (scores)
// MODE 2: fp32 out[o][p] = x + bias[o] + diag[p]*D, smem-transposed
// ---------------------------------------------------------------------------
template <int MODE>
__global__ __launch_bounds__(128, 2)
void gemm_mma(const bf16* __restrict__ A, long long sA, int ldaA,
              const bf16* __restrict__ Bm, long long sB, int ldaB,
              void* __restrict__ Cout,
              const float* __restrict__ bias, const float* __restrict__ xres,
              const float* __restrict__ dgv,
              float* __restrict__ part, float* __restrict__ num)
{
    extern __shared__ char smem[];
    uint32_t s0 = smem_u32(smem);

    int tid = threadIdx.x, lane = tid & 31, wid = tid >> 5;
    int wm = wid & 1, wn = wid >> 1;        // 2 x 2 warp grid, 64x64 each
    int b = blockIdx.z;
    int m0 = blockIdx.x * 128, n0 = blockIdx.y * 128;

    const char* Ab = (const char*)A + ((size_t)b * sA + (size_t)m0 * ldaA) * 2;
    const char* Bb = (const char*)Bm + ((size_t)b * sB + (size_t)n0 * ldaB) * 2;

    // cp.async: 512 x 16B chunks per operand tile, 4 per thread (128 threads)
    uint32_t smo[4];
    int gA[4], gB[4];
#pragma unroll
    for (int k = 0; k < 4; k++) {
        int ch = tid + k * 128;
        int r = ch >> 2, c = ch & 3;
        smo[k] = (uint32_t)(r * ROWB + c * 16);
        gA[k] = r * ldaA * 2 + c * 16;
        gB[k] = r * ldaB * 2 + c * 16;
    }

    // ldmatrix fragment addresses (validated round-3/4 scheme, mt extended to 4)
    uint32_t aoff[4][2], boff[2][4];
    {
        int ar = wm * 64 + (lane & 15);
        int ac = lane >> 4;
#pragma unroll
        for (int mt = 0; mt < 4; mt++)
#pragma unroll
            for (int ks = 0; ks < 2; ks++)
                aoff[mt][ks] = (uint32_t)((ar + mt * 16) * ROWB + (ks * 2 + ac) * 16);
        int br = wn * 64 + ((lane >> 4) & 1) * 8 + (lane & 7);
        int bc = (lane >> 3) & 1;
#pragma unroll
        for (int ks = 0; ks < 2; ks++)
#pragma unroll
            for (int p = 0; p < 4; p++)
                boff[ks][p] = (uint32_t)((br + p * 16) * ROWB + (ks * 2 + bc) * 16);
    }

    float acc[4][8][4];
#pragma unroll
    for (int i = 0; i < 4; i++)
#pragma unroll
        for (int j = 0; j < 8; j++)
#pragma unroll
            for (int l = 0; l < 4; l++) acc[i][j][l] = 0.f;

    auto issue = [&](int s, int st) {
        uint32_t ab = s0 + (uint32_t)st * (2 * TILEB);
        uint32_t bb = ab + TILEB;
        const char* ga = Ab + s * 64;
        const char* gb = Bb + s * 64;
#pragma unroll
        for (int k = 0; k < 4; k++) CPA16(ab + smo[k], ga + gA[k]);
#pragma unroll
        for (int k = 0; k < 4; k++) CPA16(bb + smo[k], gb + gB[k]);
        asm volatile("cp.async.commit_group;" ::: "memory");
    };

    issue(0, 0);
    issue(1, 1);

    for (int s = 0; s < 16; s++) {
        if (s < 15) asm volatile("cp.async.wait_group 1;" ::: "memory");
        else        asm volatile("cp.async.wait_group 0;" ::: "memory");
        __syncthreads();
        if (s + 2 < 16) issue(s + 2, (s + 2) % 3);

        uint32_t ab = s0 + (uint32_t)(s % 3) * (2 * TILEB);
        uint32_t bb = ab + TILEB;

#pragma unroll
        for (int ks = 0; ks < 2; ks++) {
            uint32_t af[4][4], bfr[4][4];
#pragma unroll
            for (int mt = 0; mt < 4; mt++)
                ldsm4(af[mt], ab + aoff[mt][ks]);
#pragma unroll
            for (int p = 0; p < 4; p++)
                ldsm4(bfr[p], bb + boff[ks][p]);
#pragma unroll
            for (int mt = 0; mt < 4; mt++)
#pragma unroll
                for (int nt = 0; nt < 8; nt++)
                    mma16816(acc[mt][nt], af[mt],
                             bfr[nt >> 1][(nt & 1) * 2], bfr[nt >> 1][(nt & 1) * 2 + 1]);
        }
    }

    // ---------------- epilogues ----------------
    int row0 = m0 + wm * 64;
    int col0 = n0 + wn * 64;
    int tr = lane >> 2, tc = (lane & 3) * 2;

    if (MODE == 0) {
        bf16* Cb = (bf16*)Cout + (size_t)b * ((size_t)PP * OC);
#pragma unroll
        for (int mt = 0; mt < 4; mt++) {
            int p1 = row0 + mt * 16 + tr, p2 = p1 + 8;
#pragma unroll
            for (int nt = 0; nt < 8; nt++) {
                int o = col0 + nt * 8 + tc;
                float b0 = bias[o], b1 = bias[o + 1];
                __nv_bfloat162 v01 = __floats2bfloat162_rn(acc[mt][nt][0] + b0,
                                                           acc[mt][nt][1] + b1);
                __nv_bfloat162 v23 = __floats2bfloat162_rn(acc[mt][nt][2] + b0,
                                                           acc[mt][nt][3] + b1);
                *(__nv_bfloat162*)(Cb + (size_t)p1 * OC + o) = v01;
                *(__nv_bfloat162*)(Cb + (size_t)p2 * OC + o) = v23;
            }
        }
    } else if (MODE == 1) {
        const float scale = 0.04419417382415922f;   // 512^-0.5
        __syncthreads();   // all warps done with smem stages
#pragma unroll
        for (int mt = 0; mt < 4; mt++)
#pragma unroll
            for (int nt = 0; nt < 8; nt++)
#pragma unroll
                for (int l = 0; l < 4; l++) {
                    float e = __expf(scale * acc[mt][nt][l]);
                    acc[mt][nt][l] = e;
                    int p = row0 + mt * 16 + tr + ((l >> 1) * 8);
                    int n = col0 + nt * 8 + tc + (l & 1);
                    if (((p >> 5) == (p & 31)) && ((n >> 5) == (n & 31)))
                        num[b * 1024 + (p & 31) * 32 + (n & 31)] = e;
                }
        // per-warp partial bins: bin (i,j) = (p&31, n&31)
        float* sp = (float*)smem;   // 4 warps x 1024 bins = 16KB
#pragma unroll
        for (int mh = 0; mh < 2; mh++)        // mt&1
#pragma unroll
            for (int rt = 0; rt < 2; rt++) {
                int i = mh * 16 + tr + rt * 8;
#pragma unroll
                for (int nh = 0; nh < 4; nh++) // nt&3
#pragma unroll
                    for (int ct = 0; ct < 2; ct++) {
                        int j = nh * 8 + tc + ct;
                        int l = rt * 2 + ct;
                        sp[wid * 1024 + i * 32 + j] =
                            acc[mh][nh][l] + acc[mh + 2][nh][l] +
                            acc[mh][nh + 4][l] + acc[mh + 2][nh + 4][l];
                    }
            }
        __syncthreads();
        float* pb = part + ((size_t)(b * 64 + blockIdx.y * 8 + blockIdx.x)) * 1024;
        for (int ij = tid; ij < 1024; ij += 128) {
            float sum = 0.f;
#pragma unroll
            for (int w = 0; w < 4; w++) sum += sp[w * 1024 + ij];
            pb[ij] = sum;
        }
    } else {
        float* ob = (float*)Cout + (size_t)b * ((size_t)CC * PP);
        const float* xb = xres + (size_t)b * ((size_t)CC * PP);
        float dgr[4][2];
#pragma unroll
        for (int mt = 0; mt < 4; mt++) {
            dgr[mt][0] = dgv[b * PP + row0 + mt * 16 + tr];
            dgr[mt][1] = dgv[b * PP + row0 + mt * 16 + tr + 8];
        }
        float (*tp)[132] = (float(*)[132])smem;   // 64 x 132 floats
        for (int h = 0; h < 2; h++) {
            __syncthreads();
            if (wn == h) {
#pragma unroll
                for (int mt = 0; mt < 4; mt++)
#pragma unroll
                    for (int nt = 0; nt < 8; nt++)
#pragma unroll
                        for (int l = 0; l < 4; l++) {
                            int o_in = nt * 8 + tc + (l & 1);
                            int p_l = wm * 64 + mt * 16 + tr + ((l >> 1) * 8);
                            tp[o_in][p_l] = dgr[mt][l >> 1] * acc[mt][nt][l];
                        }
            }
            __syncthreads();
            int r = tid >> 1;               // 0..63
            int cb = (tid & 1) * 64;        // 0 or 64
            int o = n0 + h * 64 + r;
            float bv = bias[o];
            size_t base = (size_t)o * PP + m0;
#pragma unroll
            for (int k = 0; k < 16; k++) {
                int c = cb + k * 4;
                float4 xv = *(const float4*)(xb + base + c);
                float4 w;
                w.x = xv.x + bv + tp[r][c];
                w.y = xv.y + bv + tp[r][c + 1];
                w.z = xv.z + bv + tp[r][c + 2];
                w.w = xv.w + bv + tp[r][c + 3];
                *(float4*)(ob + base + c) = w;
            }
        }
    }
}

// ---------------------------------------------------------------------------
// diag = num / sum(part)  (fixed order over 64 tiles -> deterministic)
// ---------------------------------------------------------------------------
__global__ void diag_kernel(const float* __restrict__ part,
                            const float* __restrict__ num,
                            float* __restrict__ diag)
{
    int idx = blockIdx.x * 256 + threadIdx.x;   // 16384 total
    int b = idx >> 10, ij = idx & 1023;
    const float* pp = part + (size_t)b * 64 * 1024 + ij;
    float s = 0.f;
#pragma unroll
    for (int t = 0; t < 64; t++) s += pp[t * 1024];
    diag[idx] = num[idx] / s;
}

// ---------------------------------------------------------------------------
// kernel_launch — inputs: x, Wq, bq, Wk, bk, Wv, bv, Wn, bn
// ---------------------------------------------------------------------------
extern "C" void kernel_launch(void* const* d_in, const int* in_sizes, int n_in,
                              void* d_out, int out_size)
{
    const float* x  = (const float*)d_in[0];
    const float* Wq = (const float*)d_in[1];
    const float* bq = (const float*)d_in[2];
    const float* Wk = (const float*)d_in[3];
    const float* bk = (const float*)d_in[4];
    const float* Wv = (const float*)d_in[5];
    const float* bv = (const float*)d_in[6];
    const float* Wn = (const float*)d_in[7];
    const float* bn = (const float*)d_in[8];
    float* out = (float*)d_out;

    bf16 *pnT, *pqkv, *pWT;
    float *ppart, *pnum, *pdiag, *pbcat;
    cudaGetSymbolAddress((void**)&pnT, g_nT);
    cudaGetSymbolAddress((void**)&pqkv, g_qkvT);
    cudaGetSymbolAddress((void**)&pWT, g_WT);
    cudaGetSymbolAddress((void**)&ppart, g_part);
    cudaGetSymbolAddress((void**)&pnum, g_num);
    cudaGetSymbolAddress((void**)&pdiag, g_diag);
    cudaGetSymbolAddress((void**)&pbcat, g_bcat);

    cudaFuncSetAttribute(gemm_mma<0>, cudaFuncAttributeMaxDynamicSharedMemorySize, SMEM_BYTES);
    cudaFuncSetAttribute(gemm_mma<1>, cudaFuncAttributeMaxDynamicSharedMemorySize, SMEM_BYTES);
    cudaFuncSetAttribute(gemm_mma<2>, cudaFuncAttributeMaxDynamicSharedMemorySize, SMEM_BYTES);

    // 1. Weight transposes + bias concat
    wt_kernel<<<dim3(16, 16, 4), dim3(32, 8)>>>(Wq, Wk, Wv, Wn, pWT);
    bcat_kernel<<<2, 256>>>(bq, bk, bv, pbcat);

    // 2. GroupNorm -> nT bf16
    gn_kernel<<<BB * 32, 256>>>(x, pnT);

    // 3. Merged q|k|v projection
    dim3 gp(8, 12, BB);
    gemm_mma<0><<<gp, 128, SMEM_BYTES>>>(pnT, (long long)PP * CC, CC,
                                         pWT, 0, CC,
                                         pqkv, pbcat, nullptr, nullptr,
                                         nullptr, nullptr);

    // 4. Scores with fused exp epilogue
    dim3 gs(8, 8, BB);
    gemm_mma<1><<<gs, 128, SMEM_BYTES>>>(pqkv, (long long)PP * OC, OC,
                                         pqkv + CC, (long long)PP * OC, OC,
                                         nullptr, nullptr, nullptr, nullptr,
                                         ppart, pnum);

    // 5. diag = num / denom
    diag_kernel<<<64, 256>>>(ppart, pnum, pdiag);

    // 6. Final fused projection (4 n-tiles cover all 512 channels)
    dim3 gf(8, 4, BB);
    gemm_mma<2><<<gf, 128, SMEM_BYTES>>>(pqkv + 2 * CC, (long long)PP * OC, OC,
                                         pWT + 3 * CC * CC, 0, CC,
                                         out, bn, x, pdiag,
                                         nullptr, nullptr);
}

// round 15
// speedup vs baseline: 1.3701x; 1.1184x over previous
#include <cuda_runtime.h>
#include <cuda_bf16.h>
#include <cstdint>

#define BB 16
#define CC 512
#define PP 1024
#define WS (512 * 512)   // one 512x512 weight matrix

typedef __nv_bfloat16 bf16;

// ---------------------------------------------------------------------------
// Static device scratch
// ---------------------------------------------------------------------------
__device__ __align__(1024) bf16 g_nT[(size_t)BB * PP * CC];     // [b][p][c]
__device__ __align__(1024) bf16 g_tmp[(size_t)BB * PP * CC];    // [b][p][c2]
// wbuf slots: 0=WkC 1=WnT 2=WqC 3=WvC 4=M1 5=WvnT
__device__ __align__(1024) bf16 g_wbuf[6 * WS];
__device__ __align__(128)  float g_part[(size_t)BB * 64 * 1024];
__device__ __align__(128)  float g_num[BB * 1024];
__device__ __align__(128)  float g_diag[BB * PP];
__device__ __align__(128)  float g_aq[CC], g_ak[CC], g_bvn[CC], g_c0[1];
__device__ __align__(128)  float g_u[BB * PP], g_w[BB * PP];
__device__ __align__(128)  float g_zero[CC];

// ---------------------------------------------------------------------------
// helpers
// ---------------------------------------------------------------------------
__device__ __forceinline__ uint32_t smem_u32(const void* p) {
    uint32_t a;
    asm("{ .reg .u64 t; cvta.to.shared.u64 t, %1; cvt.u32.u64 %0, t; }"
        : "=r"(a) : "l"(p));
    return a;
}

#define CPA16(sm, gm) \
    asm volatile("cp.async.cg.shared.global [%0], [%1], 16;" \
                 :: "r"(sm), "l"(gm))

__device__ __forceinline__ void ldsm4(uint32_t* r, uint32_t a) {
    asm volatile("ldmatrix.sync.aligned.m8n8.x4.shared.b16 {%0,%1,%2,%3}, [%4];"
                 : "=r"(r[0]), "=r"(r[1]), "=r"(r[2]), "=r"(r[3]) : "r"(a));
}

__device__ __forceinline__ void mma16816(float* c, const uint32_t* a,
                                         uint32_t b0, uint32_t b1) {
    asm volatile(
        "mma.sync.aligned.m16n8k16.row.col.f32.bf16.bf16.f32 "
        "{%0,%1,%2,%3}, {%4,%5,%6,%7}, {%8,%9}, {%0,%1,%2,%3};"
        : "+f"(c[0]), "+f"(c[1]), "+f"(c[2]), "+f"(c[3])
        : "r"(a[0]), "r"(a[1]), "r"(a[2]), "r"(a[3]), "r"(b0), "r"(b1));
}

#define ROWB   80
#define TILEB  (128 * ROWB)
#define SMEM_BYTES (3 * 2 * TILEB)   // 61440

// ---------------------------------------------------------------------------
// Straight bf16 converts: WkC, WqC, WvC (K-contig rows as stored)
// ---------------------------------------------------------------------------
__global__ void conv3_kernel(const float* __restrict__ Wq, const float* __restrict__ Wk,
                             const float* __restrict__ Wv, bf16* __restrict__ wbuf)
{
    int i = blockIdx.x * 256 + threadIdx.x;      // 0..262143
    wbuf[0 * WS + i] = __float2bfloat16(Wk[i]);
    wbuf[2 * WS + i] = __float2bfloat16(Wq[i]);
    wbuf[3 * WS + i] = __float2bfloat16(Wv[i]);
}

// Transpose Wn: WnT[c'][c] = bf16(Wn[c][c'])
__global__ void wtn_kernel(const float* __restrict__ Wn, bf16* __restrict__ dst)
{
    __shared__ float t[32][33];
    int c0 = blockIdx.x * 32, o0 = blockIdx.y * 32;
    for (int i = threadIdx.y; i < 32; i += 8)
        t[i][threadIdx.x] = Wn[(size_t)(c0 + i) * CC + o0 + threadIdx.x];
    __syncthreads();
    for (int i = threadIdx.y; i < 32; i += 8)
        dst[(size_t)(o0 + i) * CC + c0 + threadIdx.x] =
            __float2bfloat16(t[threadIdx.x][i]);
}

// ---------------------------------------------------------------------------
// Small vectors: aq[c]=Wq[c,:]·bk, ak[c]=Wk[c,:]·bq, bvn[c']=bv·Wn[:,c'],
// c0 = bq·bk, plus zero-bias vector.
// ---------------------------------------------------------------------------
__global__ void vec_kernel(const float* __restrict__ Wq, const float* __restrict__ Wk,
                           const float* __restrict__ Wn,
                           const float* __restrict__ bq, const float* __restrict__ bk,
                           const float* __restrict__ bv,
                           float* __restrict__ aq, float* __restrict__ ak,
                           float* __restrict__ bvn, float* __restrict__ c0,
                           float* __restrict__ zero)
{
    int c = blockIdx.x;
    int tid = threadIdx.x;
    float a1 = 0.f, a2 = 0.f, a3 = 0.f, a4 = 0.f;
    for (int o = tid; o < CC; o += 256) {
        a1 += Wq[(size_t)c * CC + o] * bk[o];
        a2 += Wk[(size_t)c * CC + o] * bq[o];
        a3 += bv[o] * Wn[(size_t)o * CC + c];
        a4 += bq[o] * bk[o];
    }
    __shared__ float s1[256], s2[256], s3[256], s4[256];
    s1[tid] = a1; s2[tid] = a2; s3[tid] = a3; s4[tid] = a4;
    __syncthreads();
    for (int off = 128; off; off >>= 1) {
        if (tid < off) {
            s1[tid] += s1[tid + off];
            s2[tid] += s2[tid + off];
            s3[tid] += s3[tid + off];
            s4[tid] += s4[tid + off];
        }
        __syncthreads();
    }
    if (tid == 0) { aq[c] = s1[0]; ak[c] = s2[0]; bvn[c] = s3[0]; }
    if (c == 0) {
        if (tid == 0) c0[0] = s4[0];
        zero[tid] = 0.f;
        zero[tid + 256] = 0.f;
    }
}

// u[row] = nT[row]·aq, w[row] = nT[row]·ak   (row = b*PP + p)
__global__ void uvw_kernel(const bf16* __restrict__ nT, const float* __restrict__ aq,
                           const float* __restrict__ ak,
                           float* __restrict__ u, float* __restrict__ w)
{
    int row = blockIdx.x * 8 + (threadIdx.x >> 5);
    int lane = threadIdx.x & 31;
    const bf16* np = nT + (size_t)row * CC;
    float su = 0.f, sw = 0.f;
    for (int c = lane; c < CC; c += 32) {
        float nv = __bfloat162float(np[c]);
        su += nv * aq[c];
        sw += nv * ak[c];
    }
#pragma unroll
    for (int off = 16; off; off >>= 1) {
        su += __shfl_xor_sync(0xFFFFFFFF, su, off);
        sw += __shfl_xor_sync(0xFFFFFFFF, sw, off);
    }
    if (lane == 0) { u[row] = su; w[row] = sw; }
}

// ---------------------------------------------------------------------------
// GroupNorm -> transposed bf16 output nT[b][p][c]
// ---------------------------------------------------------------------------
__global__ void gn_kernel(const float* __restrict__ x, bf16* __restrict__ nT)
{
    int b = blockIdx.x >> 5;
    int g = blockIdx.x & 31;
    const float* xp = x + ((size_t)b * CC + g * 16) * PP;

    float s = 0.f, s2 = 0.f;
    for (int i = threadIdx.x; i < 16384; i += 256) {
        float v = xp[i];
        s += v; s2 += v * v;
    }
    __shared__ float sh1[256], sh2[256];
    sh1[threadIdx.x] = s; sh2[threadIdx.x] = s2;
    __syncthreads();
    for (int off = 128; off; off >>= 1) {
        if (threadIdx.x < off) {
            sh1[threadIdx.x] += sh1[threadIdx.x + off];
            sh2[threadIdx.x] += sh2[threadIdx.x + off];
        }
        __syncthreads();
    }
    float mean = sh1[0] * (1.f / 16384.f);
    float var  = sh2[0] * (1.f / 16384.f) - mean * mean;
    float inv  = rsqrtf(var + 1e-5f);

    bf16* np = nT + (size_t)b * PP * CC + g * 16;
    for (int p = threadIdx.x; p < PP; p += 256) {
        uint32_t pk[8];
#pragma unroll
        for (int cc = 0; cc < 16; cc += 2) {
            float v0 = (xp[(size_t)cc * PP + p] - mean) * inv;
            float v1 = (xp[(size_t)(cc + 1) * PP + p] - mean) * inv;
            __nv_bfloat162 h = __floats2bfloat162_rn(v0, v1);
            pk[cc >> 1] = *(uint32_t*)&h;
        }
        uint4* dst = (uint4*)(np + (size_t)p * CC);
        dst[0] = make_uint4(pk[0], pk[1], pk[2], pk[3]);
        dst[1] = make_uint4(pk[4], pk[5], pk[6], pk[7]);
    }
}

// ---------------------------------------------------------------------------
// HMMA GEMM (validated R12 engine): D[m][n] = sum_{k<512} A[m][k]*B[n][k].
// CTA 128x128, warp 64x64 (2x2, 128 thr), K slab 32, 3-stage cp.async.
// MODE 0: bf16 C[m][n] = D + bias[n]   (generic ldc/sC)
// MODE 1: fused exp(scale*(D+u[m]+w[n]+c0)) -> g_part/g_num  (scores)
// MODE 2: fp32 out[n][m] = x + bias[n] + diag[m]*(D + bias2[n])
// ---------------------------------------------------------------------------
template <int MODE>
__global__ __launch_bounds__(128, 2)
void gemm_mma(const bf16* __restrict__ A, long long sA, int ldaA,
              const bf16* __restrict__ Bm, long long sB, int ldaB,
              void* __restrict__ Cout, long long sC, int ldc,
              const float* __restrict__ bias, const float* __restrict__ bias2,
              const float* __restrict__ xres, const float* __restrict__ dgv,
              const float* __restrict__ uv, const float* __restrict__ wv,
              float* __restrict__ part, float* __restrict__ num)
{
    extern __shared__ char smem[];
    uint32_t s0 = smem_u32(smem);

    int tid = threadIdx.x, lane = tid & 31, wid = tid >> 5;
    int wm = wid & 1, wn = wid >> 1;        // 2 x 2 warp grid, 64x64 each
    int b = blockIdx.z;
    int m0 = blockIdx.x * 128, n0 = blockIdx.y * 128;

    const char* Ab = (const char*)A + ((size_t)b * sA + (size_t)m0 * ldaA) * 2;
    const char* Bb = (const char*)Bm + ((size_t)b * sB + (size_t)n0 * ldaB) * 2;

    uint32_t smo[4];
    int gA[4], gB[4];
#pragma unroll
    for (int k = 0; k < 4; k++) {
        int ch = tid + k * 128;
        int r = ch >> 2, c = ch & 3;
        smo[k] = (uint32_t)(r * ROWB + c * 16);
        gA[k] = r * ldaA * 2 + c * 16;
        gB[k] = r * ldaB * 2 + c * 16;
    }

    uint32_t aoff[4][2], boff[2][4];
    {
        int ar = wm * 64 + (lane & 15);
        int ac = lane >> 4;
#pragma unroll
        for (int mt = 0; mt < 4; mt++)
#pragma unroll
            for (int ks = 0; ks < 2; ks++)
                aoff[mt][ks] = (uint32_t)((ar + mt * 16) * ROWB + (ks * 2 + ac) * 16);
        int br = wn * 64 + ((lane >> 4) & 1) * 8 + (lane & 7);
        int bc = (lane >> 3) & 1;
#pragma unroll
        for (int ks = 0; ks < 2; ks++)
#pragma unroll
            for (int p = 0; p < 4; p++)
                boff[ks][p] = (uint32_t)((br + p * 16) * ROWB + (ks * 2 + bc) * 16);
    }

    float acc[4][8][4];
#pragma unroll
    for (int i = 0; i < 4; i++)
#pragma unroll
        for (int j = 0; j < 8; j++)
#pragma unroll
            for (int l = 0; l < 4; l++) acc[i][j][l] = 0.f;

    auto issue = [&](int s, int st) {
        uint32_t ab = s0 + (uint32_t)st * (2 * TILEB);
        uint32_t bb = ab + TILEB;
        const char* ga = Ab + s * 64;
        const char* gb = Bb + s * 64;
#pragma unroll
        for (int k = 0; k < 4; k++) CPA16(ab + smo[k], ga + gA[k]);
#pragma unroll
        for (int k = 0; k < 4; k++) CPA16(bb + smo[k], gb + gB[k]);
        asm volatile("cp.async.commit_group;" ::: "memory");
    };

    issue(0, 0);
    issue(1, 1);

    for (int s = 0; s < 16; s++) {
        if (s < 15) asm volatile("cp.async.wait_group 1;" ::: "memory");
        else        asm volatile("cp.async.wait_group 0;" ::: "memory");
        __syncthreads();
        if (s + 2 < 16) issue(s + 2, (s + 2) % 3);

        uint32_t ab = s0 + (uint32_t)(s % 3) * (2 * TILEB);
        uint32_t bb = ab + TILEB;

#pragma unroll
        for (int ks = 0; ks < 2; ks++) {
            uint32_t af[4][4], bfr[4][4];
#pragma unroll
            for (int mt = 0; mt < 4; mt++)
                ldsm4(af[mt], ab + aoff[mt][ks]);
#pragma unroll
            for (int p = 0; p < 4; p++)
                ldsm4(bfr[p], bb + boff[ks][p]);
#pragma unroll
            for (int mt = 0; mt < 4; mt++)
#pragma unroll
                for (int nt = 0; nt < 8; nt++)
                    mma16816(acc[mt][nt], af[mt],
                             bfr[nt >> 1][(nt & 1) * 2], bfr[nt >> 1][(nt & 1) * 2 + 1]);
        }
    }

    // ---------------- epilogues ----------------
    int row0 = m0 + wm * 64;
    int col0 = n0 + wn * 64;
    int tr = lane >> 2, tc = (lane & 3) * 2;

    if (MODE == 0) {
        bf16* Cb = (bf16*)Cout + (size_t)b * sC;
#pragma unroll
        for (int mt = 0; mt < 4; mt++) {
            int p1 = row0 + mt * 16 + tr, p2 = p1 + 8;
#pragma unroll
            for (int nt = 0; nt < 8; nt++) {
                int o = col0 + nt * 8 + tc;
                float b0 = bias[o], b1 = bias[o + 1];
                __nv_bfloat162 v01 = __floats2bfloat162_rn(acc[mt][nt][0] + b0,
                                                           acc[mt][nt][1] + b1);
                __nv_bfloat162 v23 = __floats2bfloat162_rn(acc[mt][nt][2] + b0,
                                                           acc[mt][nt][3] + b1);
                *(__nv_bfloat162*)(Cb + (size_t)p1 * ldc + o) = v01;
                *(__nv_bfloat162*)(Cb + (size_t)p2 * ldc + o) = v23;
            }
        }
    } else if (MODE == 1) {
        const float scale = 0.04419417382415922f;   // 512^-0.5
        float c0v = bias2[0];
        const float* ub = uv + b * PP;
        const float* wb = wv + b * PP;
        __syncthreads();
#pragma unroll
        for (int mt = 0; mt < 4; mt++)
#pragma unroll
            for (int nt = 0; nt < 8; nt++)
#pragma unroll
                for (int l = 0; l < 4; l++) {
                    int p = row0 + mt * 16 + tr + ((l >> 1) * 8);
                    int n = col0 + nt * 8 + tc + (l & 1);
                    float e = __expf(scale * (acc[mt][nt][l] + ub[p] + wb[n] + c0v));
                    acc[mt][nt][l] = e;
                    if (((p >> 5) == (p & 31)) && ((n >> 5) == (n & 31)))
                        num[b * 1024 + (p & 31) * 32 + (n & 31)] = e;
                }
        float* sp = (float*)smem;   // 4 warps x 1024 bins
#pragma unroll
        for (int mh = 0; mh < 2; mh++)
#pragma unroll
            for (int rt = 0; rt < 2; rt++) {
                int i = mh * 16 + tr + rt * 8;
#pragma unroll
                for (int nh = 0; nh < 4; nh++)
#pragma unroll
                    for (int ct = 0; ct < 2; ct++) {
                        int j = nh * 8 + tc + ct;
                        int l = rt * 2 + ct;
                        sp[wid * 1024 + i * 32 + j] =
                            acc[mh][nh][l] + acc[mh + 2][nh][l] +
                            acc[mh][nh + 4][l] + acc[mh + 2][nh + 4][l];
                    }
            }
        __syncthreads();
        float* pb = part + ((size_t)(b * 64 + blockIdx.y * 8 + blockIdx.x)) * 1024;
        for (int ij = tid; ij < 1024; ij += 128) {
            float sum = 0.f;
#pragma unroll
            for (int w = 0; w < 4; w++) sum += sp[w * 1024 + ij];
            pb[ij] = sum;
        }
    } else {
        float* ob = (float*)Cout + (size_t)b * ((size_t)CC * PP);
        const float* xb = xres + (size_t)b * ((size_t)CC * PP);
        float dgr[4][2];
#pragma unroll
        for (int mt = 0; mt < 4; mt++) {
            dgr[mt][0] = dgv[b * PP + row0 + mt * 16 + tr];
            dgr[mt][1] = dgv[b * PP + row0 + mt * 16 + tr + 8];
        }
        float (*tp)[132] = (float(*)[132])smem;
        for (int h = 0; h < 2; h++) {
            __syncthreads();
            if (wn == h) {
#pragma unroll
                for (int mt = 0; mt < 4; mt++)
#pragma unroll
                    for (int nt = 0; nt < 8; nt++)
#pragma unroll
                        for (int l = 0; l < 4; l++) {
                            int o_in = nt * 8 + tc + (l & 1);
                            int p_l = wm * 64 + mt * 16 + tr + ((l >> 1) * 8);
                            float b2 = bias2[n0 + h * 64 + o_in];
                            tp[o_in][p_l] = dgr[mt][l >> 1] * (acc[mt][nt][l] + b2);
                        }
            }
            __syncthreads();
            int r = tid >> 1;               // 0..63
            int cb = (tid & 1) * 64;
            int o = n0 + h * 64 + r;
            float bv = bias[o];
            size_t base = (size_t)o * PP + m0;
#pragma unroll
            for (int k = 0; k < 16; k++) {
                int c = cb + k * 4;
                float4 xv = *(const float4*)(xb + base + c);
                float4 w;
                w.x = xv.x + bv + tp[r][c];
                w.y = xv.y + bv + tp[r][c + 1];
                w.z = xv.z + bv + tp[r][c + 2];
                w.w = xv.w + bv + tp[r][c + 3];
                *(float4*)(ob + base + c) = w;
            }
        }
    }
}

// ---------------------------------------------------------------------------
// diag = num / sum(part)  (fixed order over 64 tiles -> deterministic)
// ---------------------------------------------------------------------------
__global__ void diag_kernel(const float* __restrict__ part,
                            const float* __restrict__ num,
                            float* __restrict__ diag)
{
    int idx = blockIdx.x * 256 + threadIdx.x;
    int b = idx >> 10, ij = idx & 1023;
    const float* pp = part + (size_t)b * 64 * 1024 + ij;
    float s = 0.f;
#pragma unroll
    for (int t = 0; t < 64; t++) s += pp[t * 1024];
    diag[idx] = num[idx] / s;
}

// ---------------------------------------------------------------------------
// kernel_launch — inputs: x, Wq, bq, Wk, bk, Wv, bv, Wn, bn
// ---------------------------------------------------------------------------
extern "C" void kernel_launch(void* const* d_in, const int* in_sizes, int n_in,
                              void* d_out, int out_size)
{
    const float* x  = (const float*)d_in[0];
    const float* Wq = (const float*)d_in[1];
    const float* bq = (const float*)d_in[2];
    const float* Wk = (const float*)d_in[3];
    const float* bk = (const float*)d_in[4];
    const float* Wv = (const float*)d_in[5];
    const float* bv = (const float*)d_in[6];
    const float* Wn = (const float*)d_in[7];
    const float* bn = (const float*)d_in[8];
    float* out = (float*)d_out;

    bf16 *pnT, *ptmp, *pwb;
    float *ppart, *pnum, *pdiag, *paq, *pak, *pbvn, *pc0, *pu, *pw, *pz;
    cudaGetSymbolAddress((void**)&pnT, g_nT);
    cudaGetSymbolAddress((void**)&ptmp, g_tmp);
    cudaGetSymbolAddress((void**)&pwb, g_wbuf);
    cudaGetSymbolAddress((void**)&ppart, g_part);
    cudaGetSymbolAddress((void**)&pnum, g_num);
    cudaGetSymbolAddress((void**)&pdiag, g_diag);
    cudaGetSymbolAddress((void**)&paq, g_aq);
    cudaGetSymbolAddress((void**)&pak, g_ak);
    cudaGetSymbolAddress((void**)&pbvn, g_bvn);
    cudaGetSymbolAddress((void**)&pc0, g_c0);
    cudaGetSymbolAddress((void**)&pu, g_u);
    cudaGetSymbolAddress((void**)&pw, g_w);
    cudaGetSymbolAddress((void**)&pz, g_zero);

    cudaFuncSetAttribute(gemm_mma<0>, cudaFuncAttributeMaxDynamicSharedMemorySize, SMEM_BYTES);
    cudaFuncSetAttribute(gemm_mma<1>, cudaFuncAttributeMaxDynamicSharedMemorySize, SMEM_BYTES);
    cudaFuncSetAttribute(gemm_mma<2>, cudaFuncAttributeMaxDynamicSharedMemorySize, SMEM_BYTES);

    // 1. Weight converts + transposes + small vectors
    conv3_kernel<<<1024, 256>>>(Wq, Wk, Wv, pwb);
    wtn_kernel<<<dim3(16, 16), dim3(32, 8)>>>(Wn, pwb + 1 * WS);
    vec_kernel<<<512, 256>>>(Wq, Wk, Wn, bq, bk, bv, paq, pak, pbvn, pc0, pz);

    // 2. GroupNorm -> nT bf16
    gn_kernel<<<BB * 32, 256>>>(x, pnT);

    // 3. Weight-weight GEMMs (batched z=2): z0: M1 = Wk@Wq^T, z1: WvnT = WnT@Wv
    gemm_mma<0><<<dim3(4, 4, 2), 128, SMEM_BYTES>>>(
        pwb, WS, CC,                 // A: [WkC][WnT]
        pwb + 2 * WS, WS, CC,        // B: [WqC][WvC]
        pwb + 4 * WS, WS, CC,        // C: [M1][WvnT]
        pz, nullptr, nullptr, nullptr, nullptr, nullptr, nullptr, nullptr);

    // 4. u/w rank-1 score corrections
    uvw_kernel<<<BB * PP / 8, 256>>>(pnT, paq, pak, pu, pw);

    // 5. tmp = nT @ M1^T-form  (tmp[p][c2] = sum_c nT[p][c] * M1[c2][c])
    gemm_mma<0><<<dim3(8, 4, BB), 128, SMEM_BYTES>>>(
        pnT, (long long)PP * CC, CC,
        pwb + 4 * WS, 0, CC,
        ptmp, (long long)PP * CC, CC,
        pz, nullptr, nullptr, nullptr, nullptr, nullptr, nullptr, nullptr);

    // 6. Scores S = tmp @ nT^T with fused exp epilogue
    gemm_mma<1><<<dim3(8, 8, BB), 128, SMEM_BYTES>>>(
        ptmp, (long long)PP * CC, CC,
        pnT, (long long)PP * CC, CC,
        nullptr, 0, 0,
        nullptr, pc0, nullptr, nullptr, pu, pw, ppart, pnum);

    // 7. diag = num / denom
    diag_kernel<<<64, 256>>>(ppart, pnum, pdiag);

    // 8. Final: out[c'][p] = x + bn[c'] + diag[p]*(nT@WvnT + bvn[c'])
    gemm_mma<2><<<dim3(8, 4, BB), 128, SMEM_BYTES>>>(
        pnT, (long long)PP * CC, CC,
        pwb + 5 * WS, 0, CC,
        out, 0, 0,
        bn, pbvn, x, pdiag, nullptr, nullptr, nullptr, nullptr);
}